// round 17
// baseline (speedup 1.0000x reference)
#include <cuda_runtime.h>
#include <cstdint>

#define NN 8192
#define W64 (NN / 64)
#define GRID 128
#define BT   1024
#define DSZ  69632          // dynamic smem: max(P2: 64K+4K, P4: 42.5K)

typedef unsigned long long u64;

// Global scratch (no allocations; __device__ globals zero-init on load)
__device__ float4        g_boxes_s[NN];
__device__ float         g_conf_s[NN];
__device__ float         g_area_s[NN];
__device__ u64           g_supT[W64][NN];   // transposed suppression bitmap
__device__ u64           g_vk[NN];          // packed (key<<13|idx) of valid rows
__device__ int           g_nv;              // count of valid rows (= M)
__device__ unsigned int  g_maxbits;
__device__ unsigned int  g_bar[4];
__device__ unsigned int  g_exit;

// Replay-safe grid barrier (proven in R16): 128 blocks <= SM count, 1/SM ->
// all resident -> no deadlock. Counters reset by last exiter.
__device__ __forceinline__ void grid_barrier(int id) {
    __syncthreads();
    if (threadIdx.x == 0) {
        __threadfence();
        atomicAdd(&g_bar[id], 1u);
        while (*((volatile unsigned int*)&g_bar[id]) < GRID) { }
        __threadfence();
    }
    __syncthreads();
}

__global__ void __launch_bounds__(BT, 1)
nms_mega(const float* __restrict__ in, float* __restrict__ out) {
    extern __shared__ __align__(16) unsigned char dyn[];
    const int tid = threadIdx.x;
    const int bid = blockIdx.x;

    // ---------- P0: zero output + global conf max ----------
    {
        float4* out4 = (float4*)out;
        for (int i = bid * BT + tid; i < (NN * 5) / 4; i += GRID * BT)
            out4[i] = make_float4(0.f, 0.f, 0.f, 0.f);
        float m = 0.0f;                                  // conf >= 0
        for (int j = bid * BT + tid; j < NN; j += GRID * BT)
            m = fmaxf(m, in[j * 5 + 4]);
        #pragma unroll
        for (int o = 16; o; o >>= 1)
            m = fmaxf(m, __shfl_xor_sync(0xFFFFFFFFu, m, o));
        if ((tid & 31) == 0 && m > 0.0f)
            atomicMax(&g_maxbits, __float_as_uint(m));   // monotone bits
    }
    grid_barrier(0);

    // ---------- P1: keys + valid-list append (warp-aggregated) ----------
    {
        const float mx = __uint_as_float(*((volatile unsigned int*)&g_maxbits));
        for (int j = bid * BT + tid; j < NN; j += GRID * BT) {
            // NN % (32*stride) aligned -> warp-uniform loop trip
            float q = __fdiv_rn(in[j * 5 + 4], mx);      // IEEE div, matches jnp
            bool valid = (q >= 0.5f);
            unsigned int key = ~__float_as_uint(q);
            unsigned int bal = __ballot_sync(0xFFFFFFFFu, valid);
            if (bal) {
                int base;
                if ((tid & 31) == 0) base = atomicAdd(&g_nv, __popc(bal));
                base = __shfl_sync(0xFFFFFFFFu, base, 0);
                if (valid) {
                    int p = base + __popc(bal & ((1u << (tid & 31)) - 1u));
                    g_vk[p] = ((u64)key << 13) | (unsigned int)j;
                }
            }
        }
    }
    grid_barrier(1);

    // ---------- P2: rank valid rows among valid rows (exact + stable) ----------
    // Global rank of a valid row == rank within valid subset (all smaller keys
    // are valid). key64 unique -> strict total order, ties by original idx.
    {
        u64* vk   = (u64*)dyn;                           // up to 64 KB
        int* spart = (int*)(dyn + 65536);                // 31*32 ints
        const int M = *((volatile int*)&g_nv);
        for (int k = tid; k < M; k += BT) vk[k] = g_vk[k];
        __syncthreads();

        const int e = tid & 31;                          // element slot
        const int q = tid >> 5;                          // slice 0..31
        const int per = (M + 31) >> 5;
        const int lo = min(M, q * per), up = min(M, lo + per);

        for (int base = 0; base < M; base += GRID * 32) {
            const int vi = base + bid * 32 + e;
            const u64 Kv = (vi < M) ? vk[vi] : ~0ull;
            int r = 0;
            for (int j = lo; j < up; j++) r += (vk[j] < Kv) ? 1 : 0;
            if (q > 0) spart[(q - 1) * 32 + e] = r;
            __syncthreads();
            if (q == 0 && vi < M) {
                int rank = r;
                #pragma unroll
                for (int t = 0; t < 31; t++) rank += spart[t * 32 + e];
                const int idx = (int)(Kv & 0x1FFFull);
                const unsigned int key = (unsigned int)(Kv >> 13);
                const float* bp = in + idx * 5;
                float cx = bp[0], cy = bp[1], w = bp[2], h = bp[3];
                float hw = __fmul_rn(w, 0.5f);
                float hh = __fmul_rn(h, 0.5f);
                float x1 = __fsub_rn(cx, hw), y1 = __fsub_rn(cy, hh);
                float x2 = __fadd_rn(cx, hw), y2 = __fadd_rn(cy, hh);
                g_boxes_s[rank] = make_float4(x1, y1, x2, y2);
                g_conf_s[rank]  = __uint_as_float(~key);
                g_area_s[rank]  = __fmul_rn(__fsub_rn(x2, x1),
                                            __fsub_rn(y2, y1));
            }
            __syncthreads();
        }
    }
    grid_barrier(2);

    // ---------- P3: suppression bitmap (256j x 4 i-slices per tile) ----------
    {
        float4* sb = (float4*)dyn;                       // 4 KB
        float*  sa = (float*)(dyn + 4096);               // 1 KB
        const int M = *((volatile int*)&g_nv);
        for (int t = bid; t < 528; t += GRID) {
            int tj = 0;                                  // triangular decode
            while ((tj + 1) * (tj + 2) / 2 <= t) tj++;
            int ti = t - tj * (tj + 1) / 2;              // ti <= tj
            int j0 = tj * 256, i0 = ti * 256;
            if (j0 < M && i0 < M) {                      // block-uniform
                if (tid < 256) {
                    sb[tid] = g_boxes_s[i0 + tid];
                    sa[tid] = g_area_s[i0 + tid];
                }
                __syncthreads();
                const int jj = j0 + (tid & 255);
                const int s  = tid >> 8;                 // i-slice 0..3
                const int iend = min(jj - i0, 256);
                const int t0 = s * 64, t1 = min(iend, t0 + 64);
                if (jj < M && t1 > t0) {
                    const float4 bj = g_boxes_s[jj];
                    const float  aj = g_area_s[jj];
                    u64 mm = 0;
                    for (int tt = t0; tt < t1; tt++) {
                        float4 bi = sb[tt];
                        float ix1 = fmaxf(bi.x, bj.x);
                        float iy1 = fmaxf(bi.y, bj.y);
                        float ix2 = fminf(bi.z, bj.z);
                        float iy2 = fminf(bi.w, bj.w);
                        float iw  = fmaxf(__fsub_rn(ix2, ix1), 0.0f);
                        float ih  = fmaxf(__fsub_rn(iy2, iy1), 0.0f);
                        float inter = __fmul_rn(iw, ih);
                        float uni   = __fsub_rn(__fadd_rn(sa[tt], aj), inter);
                        // iou > 0.5 <=> inter > 0.5*max(uni,1e-9)
                        u64 hit = (inter > __fmul_rn(0.5f, fmaxf(uni, 1e-9f)))
                                      ? 1ull : 0ull;
                        mm |= hit << (tt - t0);
                    }
                    g_supT[(i0 >> 6) + s][jj] = mm;      // unique writer
                }
                __syncthreads();
            }
        }
    }
    grid_barrier(3);

    // ---------- P4: exact greedy resolve (block 0; R15-proven logic) ----------
    if (bid == 0) {
        u64* sm_   = (u64*)dyn;                          // 32 KB intra masks
        u64* sA    = (u64*)(dyn + 32768);                //  8 KB partials
        u64* keepw = (u64*)(dyn + 40960);                //  1 KB keep bitmap
        unsigned char* deadb = dyn + 41984;              //  512 B

        const int M = *((volatile int*)&g_nv);
        for (int k = tid; k < W64; k += BT) keepw[k] = 0;
        __syncthreads();

        const int jl = tid & 511;
        const int sl = tid >> 9;                         // slice 0..1

        for (int b = 0; b < 8; b++) {
            if (b * 512 >= M) break;                     // uniform
            const int j = b * 512 + jl;

            // A: cross gather vs FINAL earlier keeps, chunked early-exit
            u64 acc = 0;
            {
                int gg = sl;
                const int ge = 8 * b;
                while (gg < ge) {
                    u64 a2 = 0;
                    #pragma unroll
                    for (int u = 0; u < 8; u++) {
                        if (gg < ge) { a2 |= g_supT[gg][j] & keepw[gg]; gg += 2; }
                    }
                    acc |= a2;
                    if (acc) break;                      // row already dead
                }
            }
            sA[sl * 512 + jl] = acc;

            // B: stage intra mask words (coalesced)
            #pragma unroll
            for (int k = 0; k < 4; k++) {
                int idx = k * BT + tid;
                sm_[idx] = g_supT[8 * b + (idx >> 9)][b * 512 + (idx & 511)];
            }
            __syncthreads();

            if (tid < 512) {
                bool dead = ((sA[tid] | sA[512 + tid]) != 0ull) ||
                            (b * 512 + tid >= M);
                deadb[tid] = dead ? 1 : 0;
            }
            __syncthreads();

            // C: warp 0 resolves 8 words via bit-parallel Jacobi (exact:
            // rows settle in chain-depth order; stability = greedy fixpoint)
            if (tid < 32) {
                const int lane = tid;
                u64 kw[8];
                #pragma unroll
                for (int w = 0; w < 8; w++) {
                    const int rlo = w * 64 + lane;
                    const int rhi = rlo + 32;
                    u64 suplo = 0, suphi = 0;
                    #pragma unroll
                    for (int w2 = 0; w2 < 7; w2++) {
                        if (w2 < w) {
                            suplo |= sm_[w2 * 512 + rlo] & kw[w2];
                            suphi |= sm_[w2 * 512 + rhi] & kw[w2];
                        }
                    }
                    bool al_lo = (deadb[rlo] == 0) && (suplo == 0ull);
                    bool al_hi = (deadb[rhi] == 0) && (suphi == 0ull);
                    u64 rm_lo = (lane > 0) ? sm_[w * 512 + rlo] : 0ull;
                    u64 rm_hi = sm_[w * 512 + rhi];

                    unsigned int candl = __ballot_sync(0xFFFFFFFFu, al_lo);
                    unsigned int candh = __ballot_sync(0xFFFFFFFFu, al_hi);
                    u64 cand = (u64)candl | ((u64)candh << 32);
                    u64 k = cand;
                    while (true) {
                        bool s_lo = (rm_lo & k) != 0ull;
                        bool s_hi = (rm_hi & k) != 0ull;
                        unsigned int nl = __ballot_sync(0xFFFFFFFFu, !s_lo);
                        unsigned int nh = __ballot_sync(0xFFFFFFFFu, !s_hi);
                        u64 nk = cand & ((u64)nl | ((u64)nh << 32));
                        if (nk == k) break;
                        k = nk;
                    }
                    kw[w] = k;                           // uniform across lanes
                    if (lane == 0) keepw[8 * b + w] = k;
                }
            }
            __syncthreads();
        }

        // emit kept rows (P0 zero-filled the rest)
        #pragma unroll
        for (int k = 0; k < NN / BT; k++) {
            int p = tid + k * BT;
            if ((keepw[p >> 6] >> (p & 63)) & 1ull) {
                float4 b = g_boxes_s[p];
                float* o = out + p * 5;
                o[0] = b.x; o[1] = b.y; o[2] = b.z; o[3] = b.w;
                o[4] = g_conf_s[p];
            }
        }
    }

    // ---------- exit: last block resets all replay state ----------
    __syncthreads();
    if (tid == 0) {
        __threadfence();
        unsigned int v = atomicAdd(&g_exit, 1u);
        if (v == GRID - 1) {
            g_bar[0] = 0; g_bar[1] = 0; g_bar[2] = 0; g_bar[3] = 0;
            g_maxbits = 0;
            g_nv = 0;
            g_exit = 0;
            __threadfence();
        }
    }
}

// ---------------------------------------------------------------------------
extern "C" void kernel_launch(void* const* d_in, const int* in_sizes, int n_in,
                              void* d_out, int out_size) {
    const float* in = (const float*)d_in[0];
    float* out = (float*)d_out;
    cudaFuncSetAttribute(nms_mega,
                         cudaFuncAttributeMaxDynamicSharedMemorySize, DSZ);
    nms_mega<<<GRID, BT, DSZ>>>(in, out);                // single graph node
}